// round 2
// baseline (speedup 1.0000x reference)
#include <cuda_runtime.h>
#include <cuda_bf16.h>

// RoIAlignPool: N=1024 rois, C=256, feature (B=2, 256, 192, 192) fp32,
// pooled 7x7, sampling_ratio 2. Output (N, C, 7, 7) fp32.
//
// Thread = one output element, output-linear indexing:
//   idx = ((n*C + c)*49 + ph*7 + pw)
// -> coalesced STG; a 256-thread block spans ~5 channels of ONE roi so the
// gather footprint (~5 x 4.5KB) stays L1-resident.

#define C_CH 256
#define FH   192
#define FW   192
#define PH   7
#define PW   7
#define RATIO 2

__global__ __launch_bounds__(256)
void roi_align_kernel(const float* __restrict__ rois,
                      const float* __restrict__ feature,
                      const void*  __restrict__ stride_ptr,
                      float* __restrict__ out,
                      int total)
{
    int idx = blockIdx.x * blockDim.x + threadIdx.x;
    if (idx >= total) return;

    int s  = idx % (PH * PW);
    int c  = (idx / (PH * PW)) % C_CH;
    int n  = idx / (PH * PW * C_CH);
    int pw = s % PW;
    int ph = s / PW;

    // spatial scale: stride scalar may be int32 or float32
    int iv = *(const int*)stride_ptr;
    float stride_f = (iv > 0 && iv < 65536) ? (float)iv
                                            : *(const float*)stride_ptr;
    float scale = 1.0f / stride_f;

    const float* r = rois + n * 5;
    int   b  = (int)r[0];
    float x1 = r[1] * scale;
    float y1 = r[2] * scale;
    float x2 = r[3] * scale;
    float y2 = r[4] * scale;

    float roi_w = fmaxf(x2 - x1, 1.0f);
    float roi_h = fmaxf(y2 - y1, 1.0f);
    float bin_w = roi_w * (1.0f / PW);
    float bin_h = roi_h * (1.0f / PH);

    const float* fbase = feature + ((size_t)b * C_CH + c) * (FH * FW);

    // Precompute x-axis sample data (shared across iy)
    int   x0i[RATIO], x1i[RATIO];
    float fx[RATIO], hx[RATIO];
    bool  vx[RATIO];
    #pragma unroll
    for (int ix = 0; ix < RATIO; ix++) {
        float xx = x1 + ((float)(pw * RATIO + ix) + 0.5f) * (1.0f / RATIO) * bin_w;
        vx[ix] = (xx > -1.0f) && (xx < (float)FW);
        float cx = fminf(fmaxf(xx, 0.0f), (float)(FW - 1));
        int lo = (int)floorf(cx);
        lo = min(lo, FW - 1);
        x0i[ix] = lo;
        x1i[ix] = min(lo + 1, FW - 1);
        fx[ix]  = cx - (float)lo;
        hx[ix]  = 1.0f - fx[ix];
    }

    float acc = 0.0f;
    #pragma unroll
    for (int iy = 0; iy < RATIO; iy++) {
        float yy = y1 + ((float)(ph * RATIO + iy) + 0.5f) * (1.0f / RATIO) * bin_h;
        bool vy = (yy > -1.0f) && (yy < (float)FH);
        float cy = fminf(fmaxf(yy, 0.0f), (float)(FH - 1));
        int y0 = (int)floorf(cy);
        y0 = min(y0, FH - 1);
        int y1r = min(y0 + 1, FH - 1);
        float fy = cy - (float)y0;
        float hy = 1.0f - fy;

        const float* row0 = fbase + y0  * FW;
        const float* row1 = fbase + y1r * FW;

        #pragma unroll
        for (int ix = 0; ix < RATIO; ix++) {
            float v00 = __ldg(row0 + x0i[ix]);
            float v01 = __ldg(row0 + x1i[ix]);
            float v10 = __ldg(row1 + x0i[ix]);
            float v11 = __ldg(row1 + x1i[ix]);
            float v = hy * (hx[ix] * v00 + fx[ix] * v01)
                    + fy * (hx[ix] * v10 + fx[ix] * v11);
            if (vy && vx[ix]) acc += v;
        }
    }

    out[idx] = acc * 0.25f;
}

extern "C" void kernel_launch(void* const* d_in, const int* in_sizes, int n_in,
                              void* d_out, int out_size)
{
    const float* rois    = (const float*)d_in[0];
    const float* feature = (const float*)d_in[1];
    const void*  stridep = d_in[2];
    float* out = (float*)d_out;

    int N = in_sizes[0] / 5;
    int total = N * C_CH * PH * PW;

    int threads = 256;
    int blocks = (total + threads - 1) / threads;
    roi_align_kernel<<<blocks, threads>>>(rois, feature, stridep, out, total);
}

// round 3
// speedup vs baseline: 1.5681x; 1.5681x over previous
#include <cuda_runtime.h>
#include <cuda_bf16.h>

#define BATCH 2
#define C_CH  256
#define FH    192
#define FW    192
#define PH    7
#define PW    7
#define NBIN  (PH*PW)          // 49
#define PLANE (FH*FW)          // 36864
#define SMEM_PITCH 260         // floats per bin-row (>=256, mult of 4)

// NHWC copy of the feature map: (B, H, W, C) fp32 = 75.5 MB
__device__ float g_nhwc[BATCH * FH * FW * C_CH];

// ---------------------------------------------------------------------------
// Kernel 1: NCHW -> NHWC transpose. Per batch: transpose M[C=256][P=36864]
// to T[P][C] using 32x32 smem tiles.
// ---------------------------------------------------------------------------
__global__ __launch_bounds__(256)
void transpose_kernel(const float* __restrict__ in)
{
    __shared__ float tile[32][33];
    int pTile = blockIdx.x * 32;
    int cTile = blockIdx.y * 32;
    int b     = blockIdx.z;
    int tx = threadIdx.x;      // 0..31
    int ty = threadIdx.y;      // 0..7

    const float* src = in + (size_t)b * C_CH * PLANE;
    float* dst = g_nhwc + (size_t)b * PLANE * C_CH;

    #pragma unroll
    for (int j = 0; j < 4; j++) {
        int c = cTile + ty + 8 * j;
        tile[ty + 8 * j][tx] = src[(size_t)c * PLANE + pTile + tx];
    }
    __syncthreads();
    #pragma unroll
    for (int j = 0; j < 4; j++) {
        int p = pTile + ty + 8 * j;
        dst[(size_t)p * C_CH + cTile + tx] = tile[tx][ty + 8 * j];
    }
}

// ---------------------------------------------------------------------------
// Kernel 2: one block per roi. 256 threads = 64 channel-groups (float4) x 4
// bin-subsets. All taps are warp-uniform (y,x) -> every LDG.128 is 512B of
// contiguous channels. Results staged in smem, written coalesced.
// ---------------------------------------------------------------------------
__global__ __launch_bounds__(256)
void roi_align_nhwc_kernel(const float* __restrict__ rois,
                           const void*  __restrict__ stride_ptr,
                           float* __restrict__ out)
{
    __shared__ float sacc[NBIN * SMEM_PITCH];   // [s][c], pitch 260 -> ~51 KB

    int n   = blockIdx.x;
    int tid = threadIdx.x;
    int cg  = tid & 63;        // channel group: channels 4cg..4cg+3
    int sg  = tid >> 6;        // bin subset 0..3

    // spatial scale: stride scalar may be int32 or float32
    int iv = *(const int*)stride_ptr;
    float stride_f = (iv > 0 && iv < 65536) ? (float)iv
                                            : *(const float*)stride_ptr;
    float scale = 1.0f / stride_f;

    const float* r = rois + n * 5;
    int   b  = (int)r[0];
    float x1 = r[1] * scale;
    float y1 = r[2] * scale;
    float x2 = r[3] * scale;
    float y2 = r[4] * scale;

    float roi_w = fmaxf(x2 - x1, 1.0f);
    float roi_h = fmaxf(y2 - y1, 1.0f);
    float bin_w = roi_w * (1.0f / PW);
    float bin_h = roi_h * (1.0f / PH);

    const float4* fp = (const float4*)(g_nhwc) + (size_t)b * PLANE * (C_CH / 4);

    for (int s = sg; s < NBIN; s += 4) {
        int ph = s / PW;
        int pw = s - ph * PW;

        float ax = 0.0f, ay = 0.0f, az = 0.0f, aw = 0.0f;

        #pragma unroll
        for (int iy = 0; iy < 2; iy++) {
            float yy = y1 + ((float)(ph * 2 + iy) + 0.5f) * 0.5f * bin_h;
            bool vy = (yy > -1.0f) && (yy < (float)FH);
            float cy = fminf(fmaxf(yy, 0.0f), (float)(FH - 1));
            int y0 = (int)floorf(cy);
            y0 = min(y0, FH - 1);
            int y1r = min(y0 + 1, FH - 1);
            float fy = cy - (float)y0;
            float hy = 1.0f - fy;

            #pragma unroll
            for (int ix = 0; ix < 2; ix++) {
                float xx = x1 + ((float)(pw * 2 + ix) + 0.5f) * 0.5f * bin_w;
                bool vx = (xx > -1.0f) && (xx < (float)FW);
                float cx = fminf(fmaxf(xx, 0.0f), (float)(FW - 1));
                int x0 = (int)floorf(cx);
                x0 = min(x0, FW - 1);
                int x1r = min(x0 + 1, FW - 1);
                float fx = cx - (float)x0;
                float hx = 1.0f - fx;

                float m = (vy && vx) ? 1.0f : 0.0f;
                float w00 = m * hy * hx;
                float w01 = m * hy * fx;
                float w10 = m * fy * hx;
                float w11 = m * fy * fx;

                size_t p00 = ((size_t)(y0  * FW + x0 )) * (C_CH / 4) + cg;
                size_t p01 = ((size_t)(y0  * FW + x1r)) * (C_CH / 4) + cg;
                size_t p10 = ((size_t)(y1r * FW + x0 )) * (C_CH / 4) + cg;
                size_t p11 = ((size_t)(y1r * FW + x1r)) * (C_CH / 4) + cg;

                float4 v00 = __ldg(fp + p00);
                float4 v01 = __ldg(fp + p01);
                float4 v10 = __ldg(fp + p10);
                float4 v11 = __ldg(fp + p11);

                ax += w00 * v00.x + w01 * v01.x + w10 * v10.x + w11 * v11.x;
                ay += w00 * v00.y + w01 * v01.y + w10 * v10.y + w11 * v11.y;
                az += w00 * v00.z + w01 * v01.z + w10 * v10.z + w11 * v11.z;
                aw += w00 * v00.w + w01 * v01.w + w10 * v10.w + w11 * v11.w;
            }
        }

        // mean over 4 samples
        float4 res = make_float4(ax * 0.25f, ay * 0.25f, az * 0.25f, aw * 0.25f);
        // STS.128: lanes cg-consecutive -> conflict-free
        *(float4*)&sacc[s * SMEM_PITCH + 4 * cg] = res;
    }

    __syncthreads();

    // Coalesced write-out: out[n*12544 + c*49 + s]
    float* obase = out + (size_t)n * (C_CH * NBIN);
    for (int t = tid; t < C_CH * NBIN; t += 256) {
        int c = t / NBIN;
        int s = t - c * NBIN;
        obase[t] = sacc[s * SMEM_PITCH + c];
    }
}

extern "C" void kernel_launch(void* const* d_in, const int* in_sizes, int n_in,
                              void* d_out, int out_size)
{
    const float* rois    = (const float*)d_in[0];
    const float* feature = (const float*)d_in[1];
    const void*  stridep = d_in[2];
    float* out = (float*)d_out;

    int N = in_sizes[0] / 5;

    dim3 tgrid(PLANE / 32, C_CH / 32, BATCH);   // 1152 x 8 x 2
    dim3 tblk(32, 8);
    transpose_kernel<<<tgrid, tblk>>>(feature);

    roi_align_nhwc_kernel<<<N, 256>>>(rois, stridep, out);
}

// round 4
// speedup vs baseline: 2.3945x; 1.5270x over previous
#include <cuda_runtime.h>
#include <cuda_fp16.h>

#define BATCH 2
#define C_CH  256
#define FH    192
#define FW    192
#define PH    7
#define PW    7
#define NBIN  (PH*PW)          // 49
#define PLANE (FH*FW)          // 36864
#define SMEM_PITCH 260         // fp32 per bin-row in staging smem

// NHWC fp16 copy of the feature map: (B, H, W, C) = 37.7 MB
__device__ __half g_nhwc[BATCH * FH * FW * C_CH];

// ---------------------------------------------------------------------------
// Kernel 1: NCHW fp32 -> NHWC fp16 transpose.
// Tile: 64 channels x 32 positions. Block (32, 8).
//   load : warp reads 32 consecutive p of one channel  (128B coalesced)
//   store: warp writes 64 consecutive ch (as half2) of one p (128B coalesced)
// ---------------------------------------------------------------------------
__global__ __launch_bounds__(256)
void transpose_kernel(const float* __restrict__ in)
{
    __shared__ __half tile[32][66];   // [p-local][c-local], pad to 66 halves
    int pTile = blockIdx.x * 32;
    int cTile = blockIdx.y * 64;
    int b     = blockIdx.z;
    int tx = threadIdx.x;             // 0..31
    int ty = threadIdx.y;             // 0..7

    const float* src = in + (size_t)b * C_CH * PLANE;

    #pragma unroll
    for (int j = 0; j < 8; j++) {
        int cl = ty + 8 * j;          // 0..63
        int c  = cTile + cl;
        tile[tx][cl] = __float2half(src[(size_t)c * PLANE + pTile + tx]);
    }
    __syncthreads();

    __half2* dst = (__half2*)(g_nhwc + (size_t)b * PLANE * C_CH);
    #pragma unroll
    for (int j = 0; j < 4; j++) {
        int pl = ty + 8 * j;          // 0..31
        int p  = pTile + pl;
        __half2 h = ((const __half2*)&tile[pl][0])[tx];
        dst[(size_t)p * (C_CH / 2) + (cTile / 2) + tx] = h;
    }
}

// ---------------------------------------------------------------------------
// Kernel 2: one block per roi. 256 threads = 32 channel-groups (8 fp16 ch via
// uint4) x 8 bin-subsets. One warp covers all 256 channels of a tap.
// fp32 accumulate; results staged in smem, written coalesced.
// ---------------------------------------------------------------------------
__global__ __launch_bounds__(256)
void roi_align_nhwc_kernel(const float* __restrict__ rois,
                           const void*  __restrict__ stride_ptr,
                           float* __restrict__ out)
{
    __shared__ float sacc[NBIN * SMEM_PITCH];   // [s][c] fp32, ~51 KB

    int n   = blockIdx.x;
    int tid = threadIdx.x;
    int cg  = tid & 31;        // channel group: channels 8cg .. 8cg+7
    int sg  = tid >> 5;        // bin subset 0..7

    // spatial scale: stride scalar may be int32 or float32
    int iv = *(const int*)stride_ptr;
    float stride_f = (iv > 0 && iv < 65536) ? (float)iv
                                            : *(const float*)stride_ptr;
    float scale = 1.0f / stride_f;

    const float* r = rois + n * 5;
    int   b  = (int)r[0];
    float x1 = r[1] * scale;
    float y1 = r[2] * scale;
    float x2 = r[3] * scale;
    float y2 = r[4] * scale;

    float roi_w = fmaxf(x2 - x1, 1.0f);
    float roi_h = fmaxf(y2 - y1, 1.0f);
    float bin_w = roi_w * (1.0f / PW);
    float bin_h = roi_h * (1.0f / PH);

    const uint4* fp = (const uint4*)(g_nhwc) + (size_t)b * PLANE * (C_CH / 8);

    for (int s = sg; s < NBIN; s += 8) {
        int ph = s / PW;
        int pw = s - ph * PW;

        float acc[8];
        #pragma unroll
        for (int k = 0; k < 8; k++) acc[k] = 0.0f;

        #pragma unroll
        for (int iy = 0; iy < 2; iy++) {
            float yy = y1 + ((float)(ph * 2 + iy) + 0.5f) * 0.5f * bin_h;
            bool vy = (yy > -1.0f) && (yy < (float)FH);
            float cy = fminf(fmaxf(yy, 0.0f), (float)(FH - 1));
            int y0 = (int)floorf(cy);
            y0 = min(y0, FH - 1);
            int y1r = min(y0 + 1, FH - 1);
            float fy = cy - (float)y0;
            float hy = 1.0f - fy;

            #pragma unroll
            for (int ix = 0; ix < 2; ix++) {
                float xx = x1 + ((float)(pw * 2 + ix) + 0.5f) * 0.5f * bin_w;
                bool vx = (xx > -1.0f) && (xx < (float)FW);
                float cx = fminf(fmaxf(xx, 0.0f), (float)(FW - 1));
                int x0 = (int)floorf(cx);
                x0 = min(x0, FW - 1);
                int x1r = min(x0 + 1, FW - 1);
                float fx = cx - (float)x0;
                float hx = 1.0f - fx;

                float m = (vy && vx) ? 1.0f : 0.0f;
                float w00 = m * hy * hx;
                float w01 = m * hy * fx;
                float w10 = m * fy * hx;
                float w11 = m * fy * fx;

                uint4 q00 = __ldg(fp + ((size_t)(y0  * FW + x0 )) * (C_CH/8) + cg);
                uint4 q01 = __ldg(fp + ((size_t)(y0  * FW + x1r)) * (C_CH/8) + cg);
                uint4 q10 = __ldg(fp + ((size_t)(y1r * FW + x0 )) * (C_CH/8) + cg);
                uint4 q11 = __ldg(fp + ((size_t)(y1r * FW + x1r)) * (C_CH/8) + cg);

                const __half2* h00 = (const __half2*)&q00;
                const __half2* h01 = (const __half2*)&q01;
                const __half2* h10 = (const __half2*)&q10;
                const __half2* h11 = (const __half2*)&q11;

                #pragma unroll
                for (int k = 0; k < 4; k++) {
                    float2 f00 = __half22float2(h00[k]);
                    float2 f01 = __half22float2(h01[k]);
                    float2 f10 = __half22float2(h10[k]);
                    float2 f11 = __half22float2(h11[k]);
                    acc[2*k+0] += w00 * f00.x + w01 * f01.x + w10 * f10.x + w11 * f11.x;
                    acc[2*k+1] += w00 * f00.y + w01 * f01.y + w10 * f10.y + w11 * f11.y;
                }
            }
        }

        // mean over 4 samples; STS.128 x2, conflict-free (lanes cg-consecutive)
        float* sp = &sacc[s * SMEM_PITCH + 8 * cg];
        float4 r0 = make_float4(acc[0]*0.25f, acc[1]*0.25f, acc[2]*0.25f, acc[3]*0.25f);
        float4 r1 = make_float4(acc[4]*0.25f, acc[5]*0.25f, acc[6]*0.25f, acc[7]*0.25f);
        *(float4*)(sp + 0) = r0;
        *(float4*)(sp + 4) = r1;
    }

    __syncthreads();

    // Coalesced write-out: out[n*12544 + c*49 + s]
    float* obase = out + (size_t)n * (C_CH * NBIN);
    for (int t = tid; t < C_CH * NBIN; t += 256) {
        int c = t / NBIN;
        int s = t - c * NBIN;
        obase[t] = sacc[s * SMEM_PITCH + c];
    }
}

extern "C" void kernel_launch(void* const* d_in, const int* in_sizes, int n_in,
                              void* d_out, int out_size)
{
    const float* rois    = (const float*)d_in[0];
    const float* feature = (const float*)d_in[1];
    const void*  stridep = d_in[2];
    float* out = (float*)d_out;

    int N = in_sizes[0] / 5;

    dim3 tgrid(PLANE / 32, C_CH / 64, BATCH);   // 1152 x 4 x 2
    dim3 tblk(32, 8);
    transpose_kernel<<<tgrid, tblk>>>(feature);

    roi_align_nhwc_kernel<<<N, 256>>>(rois, stridep, out);
}

// round 5
// speedup vs baseline: 2.5581x; 1.0684x over previous
#include <cuda_runtime.h>
#include <cuda_fp16.h>

#define BATCH 2
#define C_CH  256
#define FH    192
#define FW    192
#define PH    7
#define PW    7
#define NBIN  (PH*PW)          // 49
#define PLANE (FH*FW)          // 36864
#define SMEM_PITCH 260         // fp32 per bin-row in staging smem
#define MAXBIN 25              // bins per block (split 25/24)

// NHWC fp16 copy of the feature map: (B, H, W, C) = 37.7 MB
__device__ __half g_nhwc[BATCH * FH * FW * C_CH];

// ---------------------------------------------------------------------------
// packed f32x2 helpers (sm_103a FFMA2 — only reachable via PTX)
// ---------------------------------------------------------------------------
__device__ __forceinline__ unsigned long long pack2(float a, float b) {
    unsigned long long r;
    asm("mov.b64 %0, {%1, %2};" : "=l"(r) : "f"(a), "f"(b));
    return r;
}
__device__ __forceinline__ void ffma2(unsigned long long& acc,
                                      unsigned long long v,
                                      unsigned long long w) {
    asm("fma.rn.f32x2 %0, %1, %2, %0;" : "+l"(acc) : "l"(v), "l"(w));
}
__device__ __forceinline__ float2 unpack2(unsigned long long v) {
    float2 f;
    asm("mov.b64 {%0, %1}, %2;" : "=f"(f.x), "=f"(f.y) : "l"(v));
    return f;
}

// ---------------------------------------------------------------------------
// Kernel 1: NCHW fp32 -> NHWC fp16 transpose (unchanged; ~DRAM-bound).
// ---------------------------------------------------------------------------
__global__ __launch_bounds__(256)
void transpose_kernel(const float* __restrict__ in)
{
    __shared__ __half tile[32][66];
    int pTile = blockIdx.x * 32;
    int cTile = blockIdx.y * 64;
    int b     = blockIdx.z;
    int tx = threadIdx.x;
    int ty = threadIdx.y;

    const float* src = in + (size_t)b * C_CH * PLANE;

    #pragma unroll
    for (int j = 0; j < 8; j++) {
        int cl = ty + 8 * j;
        int c  = cTile + cl;
        tile[tx][cl] = __float2half(src[(size_t)c * PLANE + pTile + tx]);
    }
    __syncthreads();

    __half2* dst = (__half2*)(g_nhwc + (size_t)b * PLANE * C_CH);
    #pragma unroll
    for (int j = 0; j < 4; j++) {
        int pl = ty + 8 * j;
        int p  = pTile + pl;
        __half2 h = ((const __half2*)&tile[pl][0])[tx];
        dst[(size_t)p * (C_CH / 2) + (cTile / 2) + tx] = h;
    }
}

// ---------------------------------------------------------------------------
// Kernel 2 body: one block handles CNT bins [S0, S0+CNT) of one roi.
// Phase A: precompute per-sample tap offsets + weights into smem.
// Phase B: thread (cg, sg) accumulates 8 fp16 channels per bin with
//          packed f32x2 FMAs. Phase C: coalesced writeout from smem.
// ---------------------------------------------------------------------------
template<int S0, int CNT>
__device__ __forceinline__
void roi_body(float* sacc, int4* goff, float4* gw,
              const float* __restrict__ rois,
              const void*  __restrict__ stride_ptr,
              float* __restrict__ out)
{
    int n   = blockIdx.x;
    int tid = threadIdx.x;
    int cg  = tid & 31;        // channel group: channels 8cg..8cg+7
    int sg  = tid >> 5;        // bin subset 0..7

    const float* r = rois + n * 5;
    int b = (int)r[0];

    // ---- Phase A: geometry precompute (one thread per sample) ----
    if (tid < CNT * 4) {
        int iv = *(const int*)stride_ptr;
        float stride_f = (iv > 0 && iv < 65536) ? (float)iv
                                                : *(const float*)stride_ptr;
        float scale = 1.0f / stride_f;

        float x1 = r[1] * scale;
        float y1 = r[2] * scale;
        float x2 = r[3] * scale;
        float y2 = r[4] * scale;
        float bin_w = fmaxf(x2 - x1, 1.0f) * (1.0f / PW);
        float bin_h = fmaxf(y2 - y1, 1.0f) * (1.0f / PH);

        int s  = S0 + (tid >> 2);
        int j  = tid & 3;
        int iy = j >> 1;
        int ix = j & 1;
        int ph = s / PW;
        int pw = s - ph * PW;

        float yy = y1 + ((float)(ph * 2 + iy) + 0.5f) * 0.5f * bin_h;
        float xx = x1 + ((float)(pw * 2 + ix) + 0.5f) * 0.5f * bin_w;
        bool vy = (yy > -1.0f) && (yy < (float)FH);
        bool vx = (xx > -1.0f) && (xx < (float)FW);

        float cy = fminf(fmaxf(yy, 0.0f), (float)(FH - 1));
        float cx = fminf(fmaxf(xx, 0.0f), (float)(FW - 1));
        int y0 = min((int)floorf(cy), FH - 1);
        int x0 = min((int)floorf(cx), FW - 1);
        int y1r = min(y0 + 1, FH - 1);
        int x1r = min(x0 + 1, FW - 1);
        float fy = cy - (float)y0;
        float fx = cx - (float)x0;
        float hy = 1.0f - fy;
        float hx = 1.0f - fx;

        float m = (vy && vx) ? 1.0f : 0.0f;
        gw[tid]   = make_float4(m*hy*hx, m*hy*fx, m*fy*hx, m*fy*fx);
        goff[tid] = make_int4((y0  * FW + x0 ) * (C_CH/8),
                              (y0  * FW + x1r) * (C_CH/8),
                              (y1r * FW + x0 ) * (C_CH/8),
                              (y1r * FW + x1r) * (C_CH/8));
    }
    __syncthreads();

    // ---- Phase B: accumulate ----
    const uint4* fp = (const uint4*)(g_nhwc) + (size_t)b * PLANE * (C_CH / 8);

    for (int sl = sg; sl < CNT; sl += 8) {
        unsigned long long acc0 = 0, acc1 = 0, acc2 = 0, acc3 = 0;

        #pragma unroll
        for (int j = 0; j < 4; j++) {
            int4   off = goff[sl * 4 + j];
            float4 w   = gw[sl * 4 + j];

            #pragma unroll
            for (int k = 0; k < 4; k++) {
                int   o  = (k == 0) ? off.x : (k == 1) ? off.y : (k == 2) ? off.z : off.w;
                float wk = (k == 0) ? w.x   : (k == 1) ? w.y   : (k == 2) ? w.z   : w.w;

                uint4 q = __ldg(fp + o + cg);
                unsigned long long w2 = pack2(wk, wk);
                const __half2* hh = (const __half2*)&q;
                float2 f0 = __half22float2(hh[0]);
                float2 f1 = __half22float2(hh[1]);
                float2 f2 = __half22float2(hh[2]);
                float2 f3 = __half22float2(hh[3]);
                ffma2(acc0, pack2(f0.x, f0.y), w2);
                ffma2(acc1, pack2(f1.x, f1.y), w2);
                ffma2(acc2, pack2(f2.x, f2.y), w2);
                ffma2(acc3, pack2(f3.x, f3.y), w2);
            }
        }

        float2 a0 = unpack2(acc0), a1 = unpack2(acc1);
        float2 a2 = unpack2(acc2), a3 = unpack2(acc3);
        float* sp = &sacc[sl * SMEM_PITCH + 8 * cg];
        *(float4*)(sp + 0) = make_float4(a0.x*0.25f, a0.y*0.25f, a1.x*0.25f, a1.y*0.25f);
        *(float4*)(sp + 4) = make_float4(a2.x*0.25f, a2.y*0.25f, a3.x*0.25f, a3.y*0.25f);
    }

    __syncthreads();

    // ---- Phase C: coalesced writeout out[n][c][S0+sl] ----
    float* obase = out + (size_t)n * (C_CH * NBIN) + S0;
    for (int t = tid; t < C_CH * CNT; t += 256) {
        int c  = t / CNT;          // constexpr CNT -> magic multiply
        int sl = t - c * CNT;
        obase[c * NBIN + sl] = sacc[sl * SMEM_PITCH + c];
    }
}

__global__ __launch_bounds__(256, 5)
void roi_align_nhwc_kernel(const float* __restrict__ rois,
                           const void*  __restrict__ stride_ptr,
                           float* __restrict__ out)
{
    __shared__ float  sacc[MAXBIN * SMEM_PITCH];  // 26 KB
    __shared__ int4   goff[MAXBIN * 4];           // 1.6 KB
    __shared__ float4 gw[MAXBIN * 4];             // 1.6 KB

    if (blockIdx.y == 0)
        roi_body<0, 25>(sacc, goff, gw, rois, stride_ptr, out);
    else
        roi_body<25, 24>(sacc, goff, gw, rois, stride_ptr, out);
}

extern "C" void kernel_launch(void* const* d_in, const int* in_sizes, int n_in,
                              void* d_out, int out_size)
{
    const float* rois    = (const float*)d_in[0];
    const float* feature = (const float*)d_in[1];
    const void*  stridep = d_in[2];
    float* out = (float*)d_out;

    int N = in_sizes[0] / 5;

    dim3 tgrid(PLANE / 32, C_CH / 64, BATCH);
    dim3 tblk(32, 8);
    transpose_kernel<<<tgrid, tblk>>>(feature);

    dim3 rgrid(N, 2);
    roi_align_nhwc_kernel<<<rgrid, 256>>>(rois, stridep, out);
}